// round 15
// baseline (speedup 1.0000x reference)
#include <cuda_runtime.h>
#include <cuda_bf16.h>
#include <cstdint>

// ---------------- scratch (device globals; no allocation allowed) ----------
#define MAX_N 100000
#define MAX_E 1600000
#define DF 128

__device__ float g_pooled[(size_t)MAX_N * DF];
__device__ float g_y1[(size_t)MAX_N * DF];
__device__ float g_stats[512];   // zeroed at head of count_kernel each call
__device__ int g_deg[MAX_N + 2];     // zeroed at tail of previous call
__device__ int g_off[MAX_N + 2];
__device__ int g_cur[MAX_N + 2];
__device__ int g_chunksum[128];      // overwritten fresh each call
__device__ volatile int g_scan_done; // reset at tail of previous call
__device__ int g_srcsorted[MAX_E];

// ==================== CSR build ==============================================

// 4 edges per thread; also zeroes g_stats
__global__ void count_kernel(const int* __restrict__ edst, int E) {
    int i = blockIdx.x * blockDim.x + threadIdx.x;
    if (i < 512) g_stats[i] = 0.f;
    int e0 = i * 4;
    if (e0 + 3 < E) {
        int4 d = *reinterpret_cast<const int4*>(edst + e0);
        atomicAdd(&g_deg[d.x], 1);
        atomicAdd(&g_deg[d.y], 1);
        atomicAdd(&g_deg[d.z], 1);
        atomicAdd(&g_deg[d.w], 1);
    } else {
        for (int e = e0; e < E; e++) atomicAdd(&g_deg[edst[e]], 1);
    }
}

// merged exclusive scan: local block scan + all-resident grid barrier.
// 98 blocks of 1024 threads — all resident simultaneously (<=148 SMs).
__global__ __launch_bounds__(1024)
void scan_merged_kernel(int total) {
    __shared__ int sm[1024];
    __shared__ int sbase;
    int t = threadIdx.x;
    int b = blockIdx.x;
    int g = b * 1024 + t;
    int x = (g < total) ? g_deg[g] : 0;
    sm[t] = x;
    __syncthreads();
#pragma unroll
    for (int o = 1; o < 1024; o <<= 1) {
        int v = (t >= o) ? sm[t - o] : 0;
        __syncthreads();
        sm[t] += v;
        __syncthreads();
    }
    // publish chunk total, then grid barrier
    if (t == 0) {
        g_chunksum[b] = sm[1023];
        __threadfence();
        atomicAdd((int*)&g_scan_done, 1);
        while (g_scan_done < gridDim.x) {}
        sbase = 0;
    }
    __syncthreads();
    if (t < b) atomicAdd(&sbase, g_chunksum[t]);
    __syncthreads();
    int excl = sbase + sm[t] - x;
    if (g < total) {
        g_off[g] = excl;
        g_cur[g] = excl;
    }
}

// 4 edges per thread
__global__ void fill_kernel(const int* __restrict__ esrc,
                            const int* __restrict__ edst, int E) {
    int i = blockIdx.x * blockDim.x + threadIdx.x;
    int e0 = i * 4;
    if (e0 + 3 < E) {
        int4 d = *reinterpret_cast<const int4*>(edst + e0);
        int4 s = *reinterpret_cast<const int4*>(esrc + e0);
        int p0 = atomicAdd(&g_cur[d.x], 1);
        int p1 = atomicAdd(&g_cur[d.y], 1);
        int p2 = atomicAdd(&g_cur[d.z], 1);
        int p3 = atomicAdd(&g_cur[d.w], 1);
        g_srcsorted[p0] = s.x;
        g_srcsorted[p1] = s.y;
        g_srcsorted[p2] = s.z;
        g_srcsorted[p3] = s.w;
    } else {
        for (int e = e0; e < E; e++) {
            int pos = atomicAdd(&g_cur[edst[e]], 1);
            g_srcsorted[pos] = esrc[e];
        }
    }
}

// ---------------- gather: pooled[i] = (1+eps)*h[i] + sum_{s in nbr(i)} h[s] -
// MLP 8: eight independent LDG.128 in flight per iteration.

__global__ void gather_kernel(const float4* __restrict__ h4,
                              const float* __restrict__ eps, int N) {
    int gwarp = (blockIdx.x * blockDim.x + threadIdx.x) >> 5;
    if (gwarp >= N) return;
    int lane = threadIdx.x & 31;
    int node = gwarp;

    float c = 1.f + eps[0];
    float4 self = __ldg(&h4[(long long)node * 32 + lane]);
    float4 acc;
    acc.x = self.x * c; acc.y = self.y * c; acc.z = self.z * c; acc.w = self.w * c;

    int begin = g_off[node];
    int end = g_off[node + 1];

    for (int j0 = begin; j0 < end; j0 += 32) {
        int cnt = min(32, end - j0);
        int myIdx = (lane < cnt) ? g_srcsorted[j0 + lane] : 0;
        int t = 0;
        for (; t + 8 <= cnt; t += 8) {
            int s0 = __shfl_sync(0xffffffff, myIdx, t + 0);
            int s1 = __shfl_sync(0xffffffff, myIdx, t + 1);
            int s2 = __shfl_sync(0xffffffff, myIdx, t + 2);
            int s3 = __shfl_sync(0xffffffff, myIdx, t + 3);
            int s4 = __shfl_sync(0xffffffff, myIdx, t + 4);
            int s5 = __shfl_sync(0xffffffff, myIdx, t + 5);
            int s6 = __shfl_sync(0xffffffff, myIdx, t + 6);
            int s7 = __shfl_sync(0xffffffff, myIdx, t + 7);
            float4 v0 = __ldg(&h4[(long long)s0 * 32 + lane]);
            float4 v1 = __ldg(&h4[(long long)s1 * 32 + lane]);
            float4 v2 = __ldg(&h4[(long long)s2 * 32 + lane]);
            float4 v3 = __ldg(&h4[(long long)s3 * 32 + lane]);
            float4 v4 = __ldg(&h4[(long long)s4 * 32 + lane]);
            float4 v5 = __ldg(&h4[(long long)s5 * 32 + lane]);
            float4 v6 = __ldg(&h4[(long long)s6 * 32 + lane]);
            float4 v7 = __ldg(&h4[(long long)s7 * 32 + lane]);
            acc.x += (v0.x + v1.x) + (v2.x + v3.x) + ((v4.x + v5.x) + (v6.x + v7.x));
            acc.y += (v0.y + v1.y) + (v2.y + v3.y) + ((v4.y + v5.y) + (v6.y + v7.y));
            acc.z += (v0.z + v1.z) + (v2.z + v3.z) + ((v4.z + v5.z) + (v6.z + v7.z));
            acc.w += (v0.w + v1.w) + (v2.w + v3.w) + ((v4.w + v5.w) + (v6.w + v7.w));
        }
        for (; t + 4 <= cnt; t += 4) {
            int s0 = __shfl_sync(0xffffffff, myIdx, t + 0);
            int s1 = __shfl_sync(0xffffffff, myIdx, t + 1);
            int s2 = __shfl_sync(0xffffffff, myIdx, t + 2);
            int s3 = __shfl_sync(0xffffffff, myIdx, t + 3);
            float4 v0 = __ldg(&h4[(long long)s0 * 32 + lane]);
            float4 v1 = __ldg(&h4[(long long)s1 * 32 + lane]);
            float4 v2 = __ldg(&h4[(long long)s2 * 32 + lane]);
            float4 v3 = __ldg(&h4[(long long)s3 * 32 + lane]);
            acc.x += (v0.x + v1.x) + (v2.x + v3.x);
            acc.y += (v0.y + v1.y) + (v2.y + v3.y);
            acc.z += (v0.z + v1.z) + (v2.z + v3.z);
            acc.w += (v0.w + v1.w) + (v2.w + v3.w);
        }
        for (; t < cnt; t++) {
            int s = __shfl_sync(0xffffffff, myIdx, t);
            float4 v = __ldg(&h4[(long long)s * 32 + lane]);
            acc.x += v.x; acc.y += v.y; acc.z += v.z; acc.w += v.w;
        }
    }
    reinterpret_cast<float4*>(g_pooled)[(long long)node * 32 + lane] = acc;
}

// ==================== GEMM1 + BN1 stats (proven (256,2) config) ==============

__global__ __launch_bounds__(256, 2)
void gemm1_kernel(const float* __restrict__ A,
                  const float* __restrict__ W,
                  const float* __restrict__ bias,
                  float* __restrict__ Y,
                  float* __restrict__ gsum, int M) {
    __shared__ float As[64][33];
    __shared__ float Ws[32][128];
    __shared__ float red[8][128];

    int tid = threadIdx.x;
    int cx = tid & 31;
    int ry = tid >> 5;
    int c0 = cx * 4;
    int r0 = ry * 8;
    int rowBase = blockIdx.x * 64;

    float acc[8][4];
#pragma unroll
    for (int i = 0; i < 8; i++)
#pragma unroll
        for (int j = 0; j < 4; j++) acc[i][j] = 0.f;

    for (int kb = 0; kb < 128; kb += 32) {
#pragma unroll
        for (int i = 0; i < 8; i++) {
            int idx = tid + i * 256;
            int r = idx >> 5, k = idx & 31;
            int row = rowBase + r;
            As[r][k] = (row < M) ? A[(long long)row * 128 + kb + k] : 0.f;
        }
#pragma unroll
        for (int i = 0; i < 16; i++) {
            int idx = tid + i * 256;
            int k = idx >> 7, cc = idx & 127;
            Ws[k][cc] = W[(long long)(kb + k) * 128 + cc];
        }
        __syncthreads();

#pragma unroll
        for (int k = 0; k < 32; k++) {
            float w[4];
#pragma unroll
            for (int j = 0; j < 4; j++) w[j] = Ws[k][c0 + j];
#pragma unroll
            for (int i = 0; i < 8; i++) {
                float a = As[r0 + i][k];
#pragma unroll
                for (int j = 0; j < 4; j++) acc[i][j] = fmaf(a, w[j], acc[i][j]);
            }
        }
        __syncthreads();
    }

    float bsum[4] = {0.f, 0.f, 0.f, 0.f};
    float bsq[4]  = {0.f, 0.f, 0.f, 0.f};
    float bv[4];
#pragma unroll
    for (int j = 0; j < 4; j++) bv[j] = bias[c0 + j];

#pragma unroll
    for (int i = 0; i < 8; i++) {
        int row = rowBase + r0 + i;
        if (row < M) {
#pragma unroll
            for (int j = 0; j < 4; j++) {
                float y = acc[i][j] + bv[j];
                Y[(long long)row * 128 + c0 + j] = y;
                bsum[j] += y;
                bsq[j]  += y * y;
            }
        }
    }

#pragma unroll
    for (int j = 0; j < 4; j++) red[ry][c0 + j] = bsum[j];
    __syncthreads();
    if (tid < 128) {
        float s = 0.f;
#pragma unroll
        for (int i = 0; i < 8; i++) s += red[i][tid];
        atomicAdd(&gsum[tid], s);
    }
    __syncthreads();
#pragma unroll
    for (int j = 0; j < 4; j++) red[ry][c0 + j] = bsq[j];
    __syncthreads();
    if (tid < 128) {
        float s = 0.f;
#pragma unroll
        for (int i = 0; i < 8; i++) s += red[i][tid];
        atomicAdd(&gsum[128 + tid], s);
    }
}

// ==================== GEMM2: finalize BN1 inline + GEMM + BN2 stats ==========

__global__ __launch_bounds__(256, 2)
void gemm2_kernel(const float* __restrict__ A,
                  const float* __restrict__ W,
                  const float* __restrict__ bias,
                  const float* __restrict__ gsumIn,
                  const float* __restrict__ gamma,
                  const float* __restrict__ beta,
                  float invN,
                  float* __restrict__ Y,
                  float* __restrict__ gsum,
                  int M) {
    __shared__ float As[64][33];
    __shared__ float Ws[32][128];
    __shared__ float red[8][128];
    __shared__ float ssf[256];

    int tid = threadIdx.x;
    int cx = tid & 31;
    int ry = tid >> 5;
    int c0 = cx * 4;
    int r0 = ry * 8;
    int rowBase = blockIdx.x * 64;

    if (tid < 128) {
        float mu = gsumIn[tid] * invN;
        float var = gsumIn[128 + tid] * invN - mu * mu;
        float rstd = rsqrtf(var + 1e-5f);
        float scale = gamma[tid] * rstd;
        ssf[tid] = scale;
        ssf[128 + tid] = fmaf(-mu, scale, beta[tid]);
    }
    __syncthreads();

    float acc[8][4];
#pragma unroll
    for (int i = 0; i < 8; i++)
#pragma unroll
        for (int j = 0; j < 4; j++) acc[i][j] = 0.f;

    for (int kb = 0; kb < 128; kb += 32) {
#pragma unroll
        for (int i = 0; i < 8; i++) {
            int idx = tid + i * 256;
            int r = idx >> 5, k = idx & 31;
            int row = rowBase + r;
            float v = 0.f;
            if (row < M) {
                v = A[(long long)row * 128 + kb + k];
                v = fmaxf(fmaf(v, ssf[kb + k], ssf[128 + kb + k]), 0.f);
            }
            As[r][k] = v;
        }
#pragma unroll
        for (int i = 0; i < 16; i++) {
            int idx = tid + i * 256;
            int k = idx >> 7, cc = idx & 127;
            Ws[k][cc] = W[(long long)(kb + k) * 128 + cc];
        }
        __syncthreads();

#pragma unroll
        for (int k = 0; k < 32; k++) {
            float w[4];
#pragma unroll
            for (int j = 0; j < 4; j++) w[j] = Ws[k][c0 + j];
#pragma unroll
            for (int i = 0; i < 8; i++) {
                float a = As[r0 + i][k];
#pragma unroll
                for (int j = 0; j < 4; j++) acc[i][j] = fmaf(a, w[j], acc[i][j]);
            }
        }
        __syncthreads();
    }

    float bsum[4] = {0.f, 0.f, 0.f, 0.f};
    float bsq[4]  = {0.f, 0.f, 0.f, 0.f};
    float bv[4];
#pragma unroll
    for (int j = 0; j < 4; j++) bv[j] = bias[c0 + j];

#pragma unroll
    for (int i = 0; i < 8; i++) {
        int row = rowBase + r0 + i;
        if (row < M) {
#pragma unroll
            for (int j = 0; j < 4; j++) {
                float y = acc[i][j] + bv[j];
                Y[(long long)row * 128 + c0 + j] = y;
                bsum[j] += y;
                bsq[j]  += y * y;
            }
        }
    }

#pragma unroll
    for (int j = 0; j < 4; j++) red[ry][c0 + j] = bsum[j];
    __syncthreads();
    if (tid < 128) {
        float s = 0.f;
#pragma unroll
        for (int i = 0; i < 8; i++) s += red[i][tid];
        atomicAdd(&gsum[tid], s);
    }
    __syncthreads();
#pragma unroll
    for (int j = 0; j < 4; j++) red[ry][c0 + j] = bsq[j];
    __syncthreads();
    if (tid < 128) {
        float s = 0.f;
#pragma unroll
        for (int i = 0; i < 8; i++) s += red[i][tid];
        atomicAdd(&gsum[128 + tid], s);
    }
}

// ---------------- apply: finalize BN2 inline + relu; tail scratch reset -----

__global__ void apply_bn_relu_kernel(float4* __restrict__ out,
                                     const float* __restrict__ gsumIn,
                                     const float* __restrict__ gamma,
                                     const float* __restrict__ beta,
                                     float invN,
                                     int total4, int degTotal) {
    __shared__ float ssf[256];
    int tid = threadIdx.x;
    if (tid < 128) {
        float mu = gsumIn[tid] * invN;
        float var = gsumIn[128 + tid] * invN - mu * mu;
        float rstd = rsqrtf(var + 1e-5f);
        float scale = gamma[tid] * rstd;
        ssf[tid] = scale;
        ssf[128 + tid] = fmaf(-mu, scale, beta[tid]);
    }
    __syncthreads();

    int i = blockIdx.x * blockDim.x + tid;
    if (i == 0) g_scan_done = 0;      // reset grid-barrier counter
    if (i < degTotal) g_deg[i] = 0;   // deg has no consumers after scan
    if (i >= total4) return;
    int c = (i * 4) & 127;
    float4 v = out[i];
    v.x = fmaxf(fmaf(v.x, ssf[c + 0], ssf[128 + c + 0]), 0.f);
    v.y = fmaxf(fmaf(v.y, ssf[c + 1], ssf[128 + c + 1]), 0.f);
    v.z = fmaxf(fmaf(v.z, ssf[c + 2], ssf[128 + c + 2]), 0.f);
    v.w = fmaxf(fmaf(v.w, ssf[c + 3], ssf[128 + c + 3]), 0.f);
    out[i] = v;
}

// ---------------- launch -----------------------------------------------------

extern "C" void kernel_launch(void* const* d_in, const int* in_sizes, int n_in,
                              void* d_out, int out_size) {
    const float* h    = (const float*)d_in[0];
    const int*  esrc  = (const int*)d_in[1];
    const int*  edst  = (const int*)d_in[2];
    const float* W1   = (const float*)d_in[3];
    const float* b1   = (const float*)d_in[4];
    const float* g1   = (const float*)d_in[5];
    const float* be1  = (const float*)d_in[6];
    const float* W2   = (const float*)d_in[7];
    const float* b2   = (const float*)d_in[8];
    const float* g2   = (const float*)d_in[9];
    const float* be2  = (const float*)d_in[10];
    const float* eps  = (const float*)d_in[11];

    int N = in_sizes[0] / DF;
    int E = in_sizes[1];
    float* out = (float*)d_out;

    float* pooled = nullptr;
    float* y1 = nullptr;
    float* stats = nullptr;
    cudaGetSymbolAddress((void**)&pooled, g_pooled);
    cudaGetSymbolAddress((void**)&y1,     g_y1);
    cudaGetSymbolAddress((void**)&stats,  g_stats);

    int total4 = N * (DF / 4);
    int scanTotal = N + 1;
    int NB = (scanTotal + 1023) / 1024;   // 98 blocks, all resident
    float invN = 1.f / (float)N;

    int edgeThreads = (E + 3) / 4;

    // 1) CSR histogram (4 edges/thread, + stats zero)
    count_kernel<<<(edgeThreads + 255) / 256, 256>>>(edst, E);
    // 2) merged scan (all-resident grid barrier)
    scan_merged_kernel<<<NB, 1024>>>(scanTotal);
    // 3) bucket fill (4 edges/thread)
    fill_kernel<<<(edgeThreads + 255) / 256, 256>>>(esrc, edst, E);
    // 4) gather-pool (MLP 8)                       [launch 4 - PROFILED]
    long long gthreads = (long long)N * 32;
    gather_kernel<<<(int)((gthreads + 255) / 256), 256>>>(
        (const float4*)h, eps, N);

    // 5) GEMM1 + BN1 stats
    int gblocks = (N + 63) / 64;
    gemm1_kernel<<<gblocks, 256>>>(pooled, W1, b1, y1, stats, N);

    // 6) GEMM2 (finalize BN1 inline) + BN2 stats
    gemm2_kernel<<<gblocks, 256>>>(
        y1, W2, b2, stats, g1, be1, invN, out, stats + 256, N);

    // 7) apply BN2+ReLU (finalize inline) + scratch reset
    apply_bn_relu_kernel<<<(total4 + 255) / 256, 256>>>(
        (float4*)out, stats + 256, g2, be2, invN, total4, scanTotal);
}

// round 16
// speedup vs baseline: 1.0505x; 1.0505x over previous
#include <cuda_runtime.h>
#include <cuda_bf16.h>
#include <cstdint>

// ---------------- scratch (device globals; no allocation allowed) ----------
#define MAX_N 100000
#define MAX_E 1600000
#define DF 128

__device__ float g_pooled[(size_t)MAX_N * DF];
__device__ float g_y1[(size_t)MAX_N * DF];
__device__ float g_stats[512];   // zeroed at head of count_kernel each call
__device__ int g_deg[MAX_N + 2];     // zeroed at tail of previous call
__device__ int g_off[MAX_N + 2];
__device__ int g_cur[MAX_N + 2];
__device__ int g_chunksum[128];      // overwritten fresh each call
__device__ volatile int g_scan_done; // reset at tail of previous call
__device__ int g_srcsorted[MAX_E];

// ==================== CSR build ==============================================

// 4 edges per thread; also zeroes g_stats
__global__ void count_kernel(const int* __restrict__ edst, int E) {
    int i = blockIdx.x * blockDim.x + threadIdx.x;
    if (i < 512) g_stats[i] = 0.f;
    int e0 = i * 4;
    if (e0 + 3 < E) {
        int4 d = *reinterpret_cast<const int4*>(edst + e0);
        atomicAdd(&g_deg[d.x], 1);
        atomicAdd(&g_deg[d.y], 1);
        atomicAdd(&g_deg[d.z], 1);
        atomicAdd(&g_deg[d.w], 1);
    } else {
        for (int e = e0; e < E; e++) atomicAdd(&g_deg[edst[e]], 1);
    }
}

// merged exclusive scan: local block scan + all-resident grid barrier.
__global__ __launch_bounds__(1024)
void scan_merged_kernel(int total) {
    __shared__ int sm[1024];
    __shared__ int sbase;
    int t = threadIdx.x;
    int b = blockIdx.x;
    int g = b * 1024 + t;
    int x = (g < total) ? g_deg[g] : 0;
    sm[t] = x;
    __syncthreads();
#pragma unroll
    for (int o = 1; o < 1024; o <<= 1) {
        int v = (t >= o) ? sm[t - o] : 0;
        __syncthreads();
        sm[t] += v;
        __syncthreads();
    }
    if (t == 0) {
        g_chunksum[b] = sm[1023];
        __threadfence();
        atomicAdd((int*)&g_scan_done, 1);
        while (g_scan_done < gridDim.x) {}
        sbase = 0;
    }
    __syncthreads();
    if (t < b) atomicAdd(&sbase, g_chunksum[t]);
    __syncthreads();
    int excl = sbase + sm[t] - x;
    if (g < total) {
        g_off[g] = excl;
        g_cur[g] = excl;
    }
}

// 4 edges per thread
__global__ void fill_kernel(const int* __restrict__ esrc,
                            const int* __restrict__ edst, int E) {
    int i = blockIdx.x * blockDim.x + threadIdx.x;
    int e0 = i * 4;
    if (e0 + 3 < E) {
        int4 d = *reinterpret_cast<const int4*>(edst + e0);
        int4 s = *reinterpret_cast<const int4*>(esrc + e0);
        int p0 = atomicAdd(&g_cur[d.x], 1);
        int p1 = atomicAdd(&g_cur[d.y], 1);
        int p2 = atomicAdd(&g_cur[d.z], 1);
        int p3 = atomicAdd(&g_cur[d.w], 1);
        g_srcsorted[p0] = s.x;
        g_srcsorted[p1] = s.y;
        g_srcsorted[p2] = s.z;
        g_srcsorted[p3] = s.w;
    } else {
        for (int e = e0; e < E; e++) {
            int pos = atomicAdd(&g_cur[edst[e]], 1);
            g_srcsorted[pos] = esrc[e];
        }
    }
}

// ---------------- gather (R14 MLP-4 version: 32 regs, 82% occ, 53us) --------

__global__ void gather_kernel(const float4* __restrict__ h4,
                              const float* __restrict__ eps, int N) {
    int gwarp = (blockIdx.x * blockDim.x + threadIdx.x) >> 5;
    if (gwarp >= N) return;
    int lane = threadIdx.x & 31;
    int node = gwarp;

    float c = 1.f + eps[0];
    float4 self = __ldg(&h4[(long long)node * 32 + lane]);
    float4 acc;
    acc.x = self.x * c; acc.y = self.y * c; acc.z = self.z * c; acc.w = self.w * c;

    int begin = g_off[node];
    int end = g_off[node + 1];

    for (int j0 = begin; j0 < end; j0 += 32) {
        int cnt = min(32, end - j0);
        int myIdx = (lane < cnt) ? g_srcsorted[j0 + lane] : 0;
        int t = 0;
        for (; t + 4 <= cnt; t += 4) {
            int s0 = __shfl_sync(0xffffffff, myIdx, t + 0);
            int s1 = __shfl_sync(0xffffffff, myIdx, t + 1);
            int s2 = __shfl_sync(0xffffffff, myIdx, t + 2);
            int s3 = __shfl_sync(0xffffffff, myIdx, t + 3);
            float4 v0 = __ldg(&h4[(long long)s0 * 32 + lane]);
            float4 v1 = __ldg(&h4[(long long)s1 * 32 + lane]);
            float4 v2 = __ldg(&h4[(long long)s2 * 32 + lane]);
            float4 v3 = __ldg(&h4[(long long)s3 * 32 + lane]);
            acc.x += v0.x + v1.x; acc.y += v0.y + v1.y;
            acc.z += v0.z + v1.z; acc.w += v0.w + v1.w;
            acc.x += v2.x + v3.x; acc.y += v2.y + v3.y;
            acc.z += v2.z + v3.z; acc.w += v2.w + v3.w;
        }
        for (; t < cnt; t++) {
            int s = __shfl_sync(0xffffffff, myIdx, t);
            float4 v = __ldg(&h4[(long long)s * 32 + lane]);
            acc.x += v.x; acc.y += v.y; acc.z += v.z; acc.w += v.w;
        }
    }
    reinterpret_cast<float4*>(g_pooled)[(long long)node * 32 + lane] = acc;
}

// ==================== GEMM1 + BN1 stats, register double-buffered ============

__global__ __launch_bounds__(256, 2)
void gemm1_kernel(const float* __restrict__ A,
                  const float* __restrict__ W,
                  const float* __restrict__ bias,
                  float* __restrict__ Y,
                  float* __restrict__ gsum, int M) {
    __shared__ float As[64][33];
    __shared__ float Ws[32][128];
    __shared__ float red[8][128];

    int tid = threadIdx.x;
    int cx = tid & 31;
    int ry = tid >> 5;
    int c0 = cx * 4;
    int r0 = ry * 8;
    int rowBase = blockIdx.x * 64;

    float acc[8][4];
#pragma unroll
    for (int i = 0; i < 8; i++)
#pragma unroll
        for (int j = 0; j < 4; j++) acc[i][j] = 0.f;

    // prefetch kb=0
    float aPre[8], wPre[16];
#pragma unroll
    for (int i = 0; i < 8; i++) {
        int idx = tid + i * 256;
        int r = idx >> 5, k = idx & 31;
        int row = rowBase + r;
        aPre[i] = (row < M) ? A[(long long)row * 128 + k] : 0.f;
    }
#pragma unroll
    for (int i = 0; i < 16; i++) {
        int idx = tid + i * 256;
        int k = idx >> 7, cc = idx & 127;
        wPre[i] = W[(long long)k * 128 + cc];
    }

    for (int kb = 0; kb < 128; kb += 32) {
#pragma unroll
        for (int i = 0; i < 8; i++) {
            int idx = tid + i * 256;
            As[idx >> 5][idx & 31] = aPre[i];
        }
#pragma unroll
        for (int i = 0; i < 16; i++) {
            int idx = tid + i * 256;
            Ws[idx >> 7][idx & 127] = wPre[i];
        }
        __syncthreads();

        // prefetch next kb while computing
        if (kb < 96) {
            int kn = kb + 32;
#pragma unroll
            for (int i = 0; i < 8; i++) {
                int idx = tid + i * 256;
                int r = idx >> 5, k = idx & 31;
                int row = rowBase + r;
                aPre[i] = (row < M) ? A[(long long)row * 128 + kn + k] : 0.f;
            }
#pragma unroll
            for (int i = 0; i < 16; i++) {
                int idx = tid + i * 256;
                int k = idx >> 7, cc = idx & 127;
                wPre[i] = W[(long long)(kn + k) * 128 + cc];
            }
        }

#pragma unroll
        for (int k = 0; k < 32; k++) {
            float w[4];
#pragma unroll
            for (int j = 0; j < 4; j++) w[j] = Ws[k][c0 + j];
#pragma unroll
            for (int i = 0; i < 8; i++) {
                float a = As[r0 + i][k];
#pragma unroll
                for (int j = 0; j < 4; j++) acc[i][j] = fmaf(a, w[j], acc[i][j]);
            }
        }
        __syncthreads();
    }

    float bsum[4] = {0.f, 0.f, 0.f, 0.f};
    float bsq[4]  = {0.f, 0.f, 0.f, 0.f};
    float bv[4];
#pragma unroll
    for (int j = 0; j < 4; j++) bv[j] = bias[c0 + j];

#pragma unroll
    for (int i = 0; i < 8; i++) {
        int row = rowBase + r0 + i;
        if (row < M) {
#pragma unroll
            for (int j = 0; j < 4; j++) {
                float y = acc[i][j] + bv[j];
                Y[(long long)row * 128 + c0 + j] = y;
                bsum[j] += y;
                bsq[j]  += y * y;
            }
        }
    }

#pragma unroll
    for (int j = 0; j < 4; j++) red[ry][c0 + j] = bsum[j];
    __syncthreads();
    if (tid < 128) {
        float s = 0.f;
#pragma unroll
        for (int i = 0; i < 8; i++) s += red[i][tid];
        atomicAdd(&gsum[tid], s);
    }
    __syncthreads();
#pragma unroll
    for (int j = 0; j < 4; j++) red[ry][c0 + j] = bsq[j];
    __syncthreads();
    if (tid < 128) {
        float s = 0.f;
#pragma unroll
        for (int i = 0; i < 8; i++) s += red[i][tid];
        atomicAdd(&gsum[128 + tid], s);
    }
}

// ==================== GEMM2: finalize BN1 inline, double-buffered ============

__global__ __launch_bounds__(256, 2)
void gemm2_kernel(const float* __restrict__ A,
                  const float* __restrict__ W,
                  const float* __restrict__ bias,
                  const float* __restrict__ gsumIn,
                  const float* __restrict__ gamma,
                  const float* __restrict__ beta,
                  float invN,
                  float* __restrict__ Y,
                  float* __restrict__ gsum,
                  int M) {
    __shared__ float As[64][33];
    __shared__ float Ws[32][128];
    __shared__ float red[8][128];
    __shared__ float ssf[256];

    int tid = threadIdx.x;
    int cx = tid & 31;
    int ry = tid >> 5;
    int c0 = cx * 4;
    int r0 = ry * 8;
    int rowBase = blockIdx.x * 64;

    if (tid < 128) {
        float mu = gsumIn[tid] * invN;
        float var = gsumIn[128 + tid] * invN - mu * mu;
        float rstd = rsqrtf(var + 1e-5f);
        float scale = gamma[tid] * rstd;
        ssf[tid] = scale;
        ssf[128 + tid] = fmaf(-mu, scale, beta[tid]);
    }
    __syncthreads();   // ssf visible to all before A-store uses it

    float acc[8][4];
#pragma unroll
    for (int i = 0; i < 8; i++)
#pragma unroll
        for (int j = 0; j < 4; j++) acc[i][j] = 0.f;

    float aPre[8], wPre[16];
#pragma unroll
    for (int i = 0; i < 8; i++) {
        int idx = tid + i * 256;
        int r = idx >> 5, k = idx & 31;
        int row = rowBase + r;
        aPre[i] = (row < M) ? A[(long long)row * 128 + k] : 0.f;
    }
#pragma unroll
    for (int i = 0; i < 16; i++) {
        int idx = tid + i * 256;
        int k = idx >> 7, cc = idx & 127;
        wPre[i] = W[(long long)k * 128 + cc];
    }

    for (int kb = 0; kb < 128; kb += 32) {
#pragma unroll
        for (int i = 0; i < 8; i++) {
            int idx = tid + i * 256;
            int r = idx >> 5, k = idx & 31;
            int row = rowBase + r;
            float v = 0.f;
            if (row < M)
                v = fmaxf(fmaf(aPre[i], ssf[kb + k], ssf[128 + kb + k]), 0.f);
            As[r][k] = v;
        }
#pragma unroll
        for (int i = 0; i < 16; i++) {
            int idx = tid + i * 256;
            Ws[idx >> 7][idx & 127] = wPre[i];
        }
        __syncthreads();

        if (kb < 96) {
            int kn = kb + 32;
#pragma unroll
            for (int i = 0; i < 8; i++) {
                int idx = tid + i * 256;
                int r = idx >> 5, k = idx & 31;
                int row = rowBase + r;
                aPre[i] = (row < M) ? A[(long long)row * 128 + kn + k] : 0.f;
            }
#pragma unroll
            for (int i = 0; i < 16; i++) {
                int idx = tid + i * 256;
                int k = idx >> 7, cc = idx & 127;
                wPre[i] = W[(long long)(kn + k) * 128 + cc];
            }
        }

#pragma unroll
        for (int k = 0; k < 32; k++) {
            float w[4];
#pragma unroll
            for (int j = 0; j < 4; j++) w[j] = Ws[k][c0 + j];
#pragma unroll
            for (int i = 0; i < 8; i++) {
                float a = As[r0 + i][k];
#pragma unroll
                for (int j = 0; j < 4; j++) acc[i][j] = fmaf(a, w[j], acc[i][j]);
            }
        }
        __syncthreads();
    }

    float bsum[4] = {0.f, 0.f, 0.f, 0.f};
    float bsq[4]  = {0.f, 0.f, 0.f, 0.f};
    float bv[4];
#pragma unroll
    for (int j = 0; j < 4; j++) bv[j] = bias[c0 + j];

#pragma unroll
    for (int i = 0; i < 8; i++) {
        int row = rowBase + r0 + i;
        if (row < M) {
#pragma unroll
            for (int j = 0; j < 4; j++) {
                float y = acc[i][j] + bv[j];
                Y[(long long)row * 128 + c0 + j] = y;
                bsum[j] += y;
                bsq[j]  += y * y;
            }
        }
    }

#pragma unroll
    for (int j = 0; j < 4; j++) red[ry][c0 + j] = bsum[j];
    __syncthreads();
    if (tid < 128) {
        float s = 0.f;
#pragma unroll
        for (int i = 0; i < 8; i++) s += red[i][tid];
        atomicAdd(&gsum[tid], s);
    }
    __syncthreads();
#pragma unroll
    for (int j = 0; j < 4; j++) red[ry][c0 + j] = bsq[j];
    __syncthreads();
    if (tid < 128) {
        float s = 0.f;
#pragma unroll
        for (int i = 0; i < 8; i++) s += red[i][tid];
        atomicAdd(&gsum[128 + tid], s);
    }
}

// ---------------- apply: finalize BN2 inline + relu; tail scratch reset -----

__global__ void apply_bn_relu_kernel(float4* __restrict__ out,
                                     const float* __restrict__ gsumIn,
                                     const float* __restrict__ gamma,
                                     const float* __restrict__ beta,
                                     float invN,
                                     int total4, int degTotal) {
    __shared__ float ssf[256];
    int tid = threadIdx.x;
    if (tid < 128) {
        float mu = gsumIn[tid] * invN;
        float var = gsumIn[128 + tid] * invN - mu * mu;
        float rstd = rsqrtf(var + 1e-5f);
        float scale = gamma[tid] * rstd;
        ssf[tid] = scale;
        ssf[128 + tid] = fmaf(-mu, scale, beta[tid]);
    }
    __syncthreads();

    int i = blockIdx.x * blockDim.x + tid;
    if (i == 0) g_scan_done = 0;
    if (i < degTotal) g_deg[i] = 0;
    if (i >= total4) return;
    int c = (i * 4) & 127;
    float4 v = out[i];
    v.x = fmaxf(fmaf(v.x, ssf[c + 0], ssf[128 + c + 0]), 0.f);
    v.y = fmaxf(fmaf(v.y, ssf[c + 1], ssf[128 + c + 1]), 0.f);
    v.z = fmaxf(fmaf(v.z, ssf[c + 2], ssf[128 + c + 2]), 0.f);
    v.w = fmaxf(fmaf(v.w, ssf[c + 3], ssf[128 + c + 3]), 0.f);
    out[i] = v;
}

// ---------------- launch -----------------------------------------------------

extern "C" void kernel_launch(void* const* d_in, const int* in_sizes, int n_in,
                              void* d_out, int out_size) {
    const float* h    = (const float*)d_in[0];
    const int*  esrc  = (const int*)d_in[1];
    const int*  edst  = (const int*)d_in[2];
    const float* W1   = (const float*)d_in[3];
    const float* b1   = (const float*)d_in[4];
    const float* g1   = (const float*)d_in[5];
    const float* be1  = (const float*)d_in[6];
    const float* W2   = (const float*)d_in[7];
    const float* b2   = (const float*)d_in[8];
    const float* g2   = (const float*)d_in[9];
    const float* be2  = (const float*)d_in[10];
    const float* eps  = (const float*)d_in[11];

    int N = in_sizes[0] / DF;
    int E = in_sizes[1];
    float* out = (float*)d_out;

    float* pooled = nullptr;
    float* y1 = nullptr;
    float* stats = nullptr;
    cudaGetSymbolAddress((void**)&pooled, g_pooled);
    cudaGetSymbolAddress((void**)&y1,     g_y1);
    cudaGetSymbolAddress((void**)&stats,  g_stats);

    int total4 = N * (DF / 4);
    int scanTotal = N + 1;
    int NB = (scanTotal + 1023) / 1024;
    float invN = 1.f / (float)N;
    int edgeThreads = (E + 3) / 4;

    // 1) CSR histogram (+ stats zero)
    count_kernel<<<(edgeThreads + 255) / 256, 256>>>(edst, E);
    // 2) merged scan
    scan_merged_kernel<<<NB, 1024>>>(scanTotal);
    // 3) bucket fill
    fill_kernel<<<(edgeThreads + 255) / 256, 256>>>(esrc, edst, E);
    // 4) gather-pool (MLP 4)                       [launch 4 - PROFILED]
    long long gthreads = (long long)N * 32;
    gather_kernel<<<(int)((gthreads + 255) / 256), 256>>>(
        (const float4*)h, eps, N);

    // 5) GEMM1 + BN1 stats (double-buffered)
    int gblocks = (N + 63) / 64;
    gemm1_kernel<<<gblocks, 256>>>(pooled, W1, b1, y1, stats, N);

    // 6) GEMM2 (finalize BN1 inline, double-buffered) + BN2 stats
    gemm2_kernel<<<gblocks, 256>>>(
        y1, W2, b2, stats, g1, be1, invN, out, stats + 256, N);

    // 7) apply BN2+ReLU (finalize inline) + scratch reset
    apply_bn_relu_kernel<<<(total4 + 255) / 256, 256>>>(
        (float4*)out, stats + 256, g2, be2, invN, total4, scanTotal);
}

// round 17
// speedup vs baseline: 1.1290x; 1.0748x over previous
#include <cuda_runtime.h>
#include <cuda_bf16.h>
#include <cstdint>

// ---------------- scratch (device globals; no allocation allowed) ----------
#define MAX_N 100000
#define MAX_E 1600000
#define DF 128

__device__ float g_pooled[(size_t)MAX_N * DF];
__device__ float g_y1[(size_t)MAX_N * DF];
__device__ float g_stats[512];   // zeroed at head of count_kernel each call
__device__ int g_deg[MAX_N + 2];     // zeroed at tail of previous call
__device__ int g_off[MAX_N + 2];
__device__ int g_cur[MAX_N + 2];
__device__ int g_chunksum[128];      // overwritten fresh each call
__device__ volatile int g_scan_done; // reset at tail of previous call
__device__ int g_srcsorted[MAX_E];

// ==================== packed f32x2 helpers ===================================

__device__ __forceinline__ void ffma2(unsigned long long& d,
                                      unsigned long long a,
                                      unsigned long long b) {
    asm("fma.rn.f32x2 %0, %1, %2, %0;" : "+l"(d) : "l"(a), "l"(b));
}

__device__ __forceinline__ unsigned long long pack2(float x) {
    unsigned long long r;
    asm("mov.b64 %0, {%1, %1};" : "=l"(r) : "f"(x));
    return r;
}

__device__ __forceinline__ void unpack2(unsigned long long v, float& lo, float& hi) {
    asm("mov.b64 {%0, %1}, %2;" : "=f"(lo), "=f"(hi) : "l"(v));
}

// ==================== CSR build ==============================================

__global__ void count_kernel(const int* __restrict__ edst, int E) {
    int i = blockIdx.x * blockDim.x + threadIdx.x;
    if (i < 512) g_stats[i] = 0.f;
    int e0 = i * 4;
    if (e0 + 3 < E) {
        int4 d = *reinterpret_cast<const int4*>(edst + e0);
        atomicAdd(&g_deg[d.x], 1);
        atomicAdd(&g_deg[d.y], 1);
        atomicAdd(&g_deg[d.z], 1);
        atomicAdd(&g_deg[d.w], 1);
    } else {
        for (int e = e0; e < E; e++) atomicAdd(&g_deg[edst[e]], 1);
    }
}

__global__ __launch_bounds__(1024)
void scan_merged_kernel(int total) {
    __shared__ int sm[1024];
    __shared__ int sbase;
    int t = threadIdx.x;
    int b = blockIdx.x;
    int g = b * 1024 + t;
    int x = (g < total) ? g_deg[g] : 0;
    sm[t] = x;
    __syncthreads();
#pragma unroll
    for (int o = 1; o < 1024; o <<= 1) {
        int v = (t >= o) ? sm[t - o] : 0;
        __syncthreads();
        sm[t] += v;
        __syncthreads();
    }
    if (t == 0) {
        g_chunksum[b] = sm[1023];
        __threadfence();
        atomicAdd((int*)&g_scan_done, 1);
        while (g_scan_done < gridDim.x) {}
        sbase = 0;
    }
    __syncthreads();
    if (t < b) atomicAdd(&sbase, g_chunksum[t]);
    __syncthreads();
    int excl = sbase + sm[t] - x;
    if (g < total) {
        g_off[g] = excl;
        g_cur[g] = excl;
    }
}

__global__ void fill_kernel(const int* __restrict__ esrc,
                            const int* __restrict__ edst, int E) {
    int i = blockIdx.x * blockDim.x + threadIdx.x;
    int e0 = i * 4;
    if (e0 + 3 < E) {
        int4 d = *reinterpret_cast<const int4*>(edst + e0);
        int4 s = *reinterpret_cast<const int4*>(esrc + e0);
        int p0 = atomicAdd(&g_cur[d.x], 1);
        int p1 = atomicAdd(&g_cur[d.y], 1);
        int p2 = atomicAdd(&g_cur[d.z], 1);
        int p3 = atomicAdd(&g_cur[d.w], 1);
        g_srcsorted[p0] = s.x;
        g_srcsorted[p1] = s.y;
        g_srcsorted[p2] = s.z;
        g_srcsorted[p3] = s.w;
    } else {
        for (int e = e0; e < E; e++) {
            int pos = atomicAdd(&g_cur[edst[e]], 1);
            g_srcsorted[pos] = esrc[e];
        }
    }
}

// ---------------- gather (measured-best MLP-4, 32 regs) ---------------------

__global__ void gather_kernel(const float4* __restrict__ h4,
                              const float* __restrict__ eps, int N) {
    int gwarp = (blockIdx.x * blockDim.x + threadIdx.x) >> 5;
    if (gwarp >= N) return;
    int lane = threadIdx.x & 31;
    int node = gwarp;

    float c = 1.f + eps[0];
    float4 self = __ldg(&h4[(long long)node * 32 + lane]);
    float4 acc;
    acc.x = self.x * c; acc.y = self.y * c; acc.z = self.z * c; acc.w = self.w * c;

    int begin = g_off[node];
    int end = g_off[node + 1];

    for (int j0 = begin; j0 < end; j0 += 32) {
        int cnt = min(32, end - j0);
        int myIdx = (lane < cnt) ? g_srcsorted[j0 + lane] : 0;
        int t = 0;
        for (; t + 4 <= cnt; t += 4) {
            int s0 = __shfl_sync(0xffffffff, myIdx, t + 0);
            int s1 = __shfl_sync(0xffffffff, myIdx, t + 1);
            int s2 = __shfl_sync(0xffffffff, myIdx, t + 2);
            int s3 = __shfl_sync(0xffffffff, myIdx, t + 3);
            float4 v0 = __ldg(&h4[(long long)s0 * 32 + lane]);
            float4 v1 = __ldg(&h4[(long long)s1 * 32 + lane]);
            float4 v2 = __ldg(&h4[(long long)s2 * 32 + lane]);
            float4 v3 = __ldg(&h4[(long long)s3 * 32 + lane]);
            acc.x += v0.x + v1.x; acc.y += v0.y + v1.y;
            acc.z += v0.z + v1.z; acc.w += v0.w + v1.w;
            acc.x += v2.x + v3.x; acc.y += v2.y + v3.y;
            acc.z += v2.z + v3.z; acc.w += v2.w + v3.w;
        }
        for (; t < cnt; t++) {
            int s = __shfl_sync(0xffffffff, myIdx, t);
            float4 v = __ldg(&h4[(long long)s * 32 + lane]);
            acc.x += v.x; acc.y += v.y; acc.z += v.z; acc.w += v.w;
        }
    }
    reinterpret_cast<float4*>(g_pooled)[(long long)node * 32 + lane] = acc;
}

// ==================== f32x2 GEMM + fused BN stats =============================
// As stored as row-PAIRS: As2f[pair*66 + k*2 + (row&1)], pair = row>>1.
// Each thread: 4 row-pairs (8 rows) x 4 cols, acc packed as 16 b64.
// a-operand: LDS.64 of a pre-packed pair (warp-broadcast).
// w-operand: LDS.128 of 4 cols, packed {w,w} per col.

#define ASF_STRIDE 66   // floats per pair row (32 k * 2 + 2 pad)

template <bool TRANSFORM>
__global__ __launch_bounds__(256, 2)
void gemm_f32x2_kernel(const float* __restrict__ A,
                       const float* __restrict__ W,
                       const float* __restrict__ bias,
                       const float* __restrict__ gsumIn,  // BN stats in (TRANSFORM)
                       const float* __restrict__ gamma,
                       const float* __restrict__ beta,
                       float invN,
                       float* __restrict__ Y,
                       float* __restrict__ gsum,
                       int M) {
    __shared__ float As2f[32 * ASF_STRIDE];
    __shared__ float Ws[32][128];
    __shared__ float red[8][128];
    __shared__ float ssf[256];

    int tid = threadIdx.x;
    int cx = tid & 31;
    int ry = tid >> 5;
    int c0 = cx * 4;
    int p0 = ry * 4;          // first row-pair
    int rowBase = blockIdx.x * 64;

    if (TRANSFORM) {
        if (tid < 128) {
            float mu = gsumIn[tid] * invN;
            float var = gsumIn[128 + tid] * invN - mu * mu;
            float rstd = rsqrtf(var + 1e-5f);
            float scale = gamma[tid] * rstd;
            ssf[tid] = scale;
            ssf[128 + tid] = fmaf(-mu, scale, beta[tid]);
        }
        __syncthreads();
    }

    unsigned long long acc2[4][4];
#pragma unroll
    for (int p = 0; p < 4; p++)
#pragma unroll
        for (int j = 0; j < 4; j++) acc2[p][j] = 0ull;

    // prefetch kb=0
    float aPre[8], wPre[16];
#pragma unroll
    for (int i = 0; i < 8; i++) {
        int idx = tid + i * 256;
        int r = idx >> 5, k = idx & 31;
        int row = rowBase + r;
        aPre[i] = (row < M) ? A[(long long)row * 128 + k] : 0.f;
    }
#pragma unroll
    for (int i = 0; i < 16; i++) {
        int idx = tid + i * 256;
        int k = idx >> 7, cc = idx & 127;
        wPre[i] = W[(long long)k * 128 + cc];
    }

    for (int kb = 0; kb < 128; kb += 32) {
#pragma unroll
        for (int i = 0; i < 8; i++) {
            int idx = tid + i * 256;
            int r = idx >> 5, k = idx & 31;
            float v = aPre[i];
            if (TRANSFORM) {
                int row = rowBase + r;
                v = (row < M) ? fmaxf(fmaf(v, ssf[kb + k], ssf[128 + kb + k]), 0.f)
                              : 0.f;
            }
            As2f[(r >> 1) * ASF_STRIDE + k * 2 + (r & 1)] = v;
        }
#pragma unroll
        for (int i = 0; i < 16; i++) {
            int idx = tid + i * 256;
            Ws[idx >> 7][idx & 127] = wPre[i];
        }
        __syncthreads();

        if (kb < 96) {
            int kn = kb + 32;
#pragma unroll
            for (int i = 0; i < 8; i++) {
                int idx = tid + i * 256;
                int r = idx >> 5, k = idx & 31;
                int row = rowBase + r;
                aPre[i] = (row < M) ? A[(long long)row * 128 + kn + k] : 0.f;
            }
#pragma unroll
            for (int i = 0; i < 16; i++) {
                int idx = tid + i * 256;
                int k = idx >> 7, cc = idx & 127;
                wPre[i] = W[(long long)(kn + k) * 128 + cc];
            }
        }

#pragma unroll
        for (int k = 0; k < 32; k++) {
            float4 w = *reinterpret_cast<const float4*>(&Ws[k][c0]);
            unsigned long long w2[4];
            w2[0] = pack2(w.x); w2[1] = pack2(w.y);
            w2[2] = pack2(w.z); w2[3] = pack2(w.w);
            unsigned long long a2[4];
#pragma unroll
            for (int p = 0; p < 4; p++)
                a2[p] = *reinterpret_cast<const unsigned long long*>(
                    &As2f[(p0 + p) * ASF_STRIDE + k * 2]);
#pragma unroll
            for (int p = 0; p < 4; p++)
#pragma unroll
                for (int j = 0; j < 4; j++)
                    ffma2(acc2[p][j], a2[p], w2[j]);
        }
        __syncthreads();
    }

    // ---- epilogue: unpack, bias, store, fused BN stats
    float bsum[4] = {0.f, 0.f, 0.f, 0.f};
    float bsq[4]  = {0.f, 0.f, 0.f, 0.f};
    float bv[4];
#pragma unroll
    for (int j = 0; j < 4; j++) bv[j] = bias[c0 + j];

#pragma unroll
    for (int p = 0; p < 4; p++) {
        int rlo = rowBase + (p0 + p) * 2;
        int rhi = rlo + 1;
        float ylo[4], yhi[4];
#pragma unroll
        for (int j = 0; j < 4; j++) {
            float lo, hi;
            unpack2(acc2[p][j], lo, hi);
            ylo[j] = lo + bv[j];
            yhi[j] = hi + bv[j];
        }
        if (rlo < M) {
#pragma unroll
            for (int j = 0; j < 4; j++) {
                Y[(long long)rlo * 128 + c0 + j] = ylo[j];
                bsum[j] += ylo[j];
                bsq[j]  += ylo[j] * ylo[j];
            }
        }
        if (rhi < M) {
#pragma unroll
            for (int j = 0; j < 4; j++) {
                Y[(long long)rhi * 128 + c0 + j] = yhi[j];
                bsum[j] += yhi[j];
                bsq[j]  += yhi[j] * yhi[j];
            }
        }
    }

#pragma unroll
    for (int j = 0; j < 4; j++) red[ry][c0 + j] = bsum[j];
    __syncthreads();
    if (tid < 128) {
        float s = 0.f;
#pragma unroll
        for (int i = 0; i < 8; i++) s += red[i][tid];
        atomicAdd(&gsum[tid], s);
    }
    __syncthreads();
#pragma unroll
    for (int j = 0; j < 4; j++) red[ry][c0 + j] = bsq[j];
    __syncthreads();
    if (tid < 128) {
        float s = 0.f;
#pragma unroll
        for (int i = 0; i < 8; i++) s += red[i][tid];
        atomicAdd(&gsum[128 + tid], s);
    }
}

// ---------------- apply: finalize BN2 inline + relu; tail scratch reset -----

__global__ void apply_bn_relu_kernel(float4* __restrict__ out,
                                     const float* __restrict__ gsumIn,
                                     const float* __restrict__ gamma,
                                     const float* __restrict__ beta,
                                     float invN,
                                     int total4, int degTotal) {
    __shared__ float ssf[256];
    int tid = threadIdx.x;
    if (tid < 128) {
        float mu = gsumIn[tid] * invN;
        float var = gsumIn[128 + tid] * invN - mu * mu;
        float rstd = rsqrtf(var + 1e-5f);
        float scale = gamma[tid] * rstd;
        ssf[tid] = scale;
        ssf[128 + tid] = fmaf(-mu, scale, beta[tid]);
    }
    __syncthreads();

    int i = blockIdx.x * blockDim.x + tid;
    if (i == 0) g_scan_done = 0;
    if (i < degTotal) g_deg[i] = 0;
    if (i >= total4) return;
    int c = (i * 4) & 127;
    float4 v = out[i];
    v.x = fmaxf(fmaf(v.x, ssf[c + 0], ssf[128 + c + 0]), 0.f);
    v.y = fmaxf(fmaf(v.y, ssf[c + 1], ssf[128 + c + 1]), 0.f);
    v.z = fmaxf(fmaf(v.z, ssf[c + 2], ssf[128 + c + 2]), 0.f);
    v.w = fmaxf(fmaf(v.w, ssf[c + 3], ssf[128 + c + 3]), 0.f);
    out[i] = v;
}

// ---------------- launch -----------------------------------------------------

extern "C" void kernel_launch(void* const* d_in, const int* in_sizes, int n_in,
                              void* d_out, int out_size) {
    const float* h    = (const float*)d_in[0];
    const int*  esrc  = (const int*)d_in[1];
    const int*  edst  = (const int*)d_in[2];
    const float* W1   = (const float*)d_in[3];
    const float* b1   = (const float*)d_in[4];
    const float* g1   = (const float*)d_in[5];
    const float* be1  = (const float*)d_in[6];
    const float* W2   = (const float*)d_in[7];
    const float* b2   = (const float*)d_in[8];
    const float* g2   = (const float*)d_in[9];
    const float* be2  = (const float*)d_in[10];
    const float* eps  = (const float*)d_in[11];

    int N = in_sizes[0] / DF;
    int E = in_sizes[1];
    float* out = (float*)d_out;

    float* pooled = nullptr;
    float* y1 = nullptr;
    float* stats = nullptr;
    cudaGetSymbolAddress((void**)&pooled, g_pooled);
    cudaGetSymbolAddress((void**)&y1,     g_y1);
    cudaGetSymbolAddress((void**)&stats,  g_stats);

    int total4 = N * (DF / 4);
    int scanTotal = N + 1;
    int NB = (scanTotal + 1023) / 1024;
    float invN = 1.f / (float)N;
    int edgeThreads = (E + 3) / 4;

    // 1) CSR histogram (+ stats zero)
    count_kernel<<<(edgeThreads + 255) / 256, 256>>>(edst, E);
    // 2) merged scan
    scan_merged_kernel<<<NB, 1024>>>(scanTotal);
    // 3) bucket fill
    fill_kernel<<<(edgeThreads + 255) / 256, 256>>>(esrc, edst, E);
    // 4) gather-pool                               [launch 4 - PROFILED]
    long long gthreads = (long long)N * 32;
    gather_kernel<<<(int)((gthreads + 255) / 256), 256>>>(
        (const float4*)h, eps, N);

    // 5) GEMM1 (f32x2) + BN1 stats
    int gblocks = (N + 63) / 64;
    gemm_f32x2_kernel<false><<<gblocks, 256>>>(
        pooled, W1, b1, nullptr, nullptr, nullptr, invN, y1, stats, N);

    // 6) GEMM2 (f32x2, finalize BN1 inline) + BN2 stats
    gemm_f32x2_kernel<true><<<gblocks, 256>>>(
        y1, W2, b2, stats, g1, be1, invN, out, stats + 256, N);

    // 7) apply BN2+ReLU (finalize inline) + scratch reset
    apply_bn_relu_kernel<<<(total4 + 255) / 256, 256>>>(
        (float4*)out, stats + 256, g2, be2, invN, total4, scanTotal);
}